// round 1
// baseline (speedup 1.0000x reference)
#include <cuda_runtime.h>
#include <cuda_bf16.h>
#include <math.h>

// ---------------------------------------------------------------------------
// Problem constants
// ---------------------------------------------------------------------------
#define D_MODEL 1024
#define N_HEADS 16
#define D_HEAD  64
#define D_FF    2752
#define BATCH   2
#define SEQ     2048
#define ROWS    (BATCH * SEQ)          // 4096
#define EPS     1e-5f

// ---------------------------------------------------------------------------
// Scratch (device globals; no allocation allowed)
// ---------------------------------------------------------------------------
__device__ float g_xn  [ROWS * D_MODEL];
__device__ float g_q   [ROWS * D_MODEL];
__device__ float g_k   [ROWS * D_MODEL];
__device__ float g_v   [ROWS * D_MODEL];
__device__ float g_attn[ROWS * D_MODEL];
__device__ float g_hres[ROWS * D_MODEL];
__device__ float g_hn  [ROWS * D_MODEL];
__device__ float g_gate[ROWS * D_FF];

// ---------------------------------------------------------------------------
// RMSNorm: one block per row of 1024, 256 threads, float4
// ---------------------------------------------------------------------------
__global__ void rmsnorm_kernel(const float* __restrict__ X,
                               const float* __restrict__ G,
                               float* __restrict__ Y)
{
    int row = blockIdx.x;
    int tid = threadIdx.x;                       // 256
    const float4* xp = reinterpret_cast<const float4*>(X + (size_t)row * D_MODEL);
    const float4* gp = reinterpret_cast<const float4*>(G);
    float4*       yp = reinterpret_cast<float4*>(Y + (size_t)row * D_MODEL);

    float4 v = xp[tid];
    float ss = v.x * v.x + v.y * v.y + v.z * v.z + v.w * v.w;

    // warp reduce
    #pragma unroll
    for (int off = 16; off > 0; off >>= 1)
        ss += __shfl_xor_sync(0xffffffffu, ss, off);

    __shared__ float wsum[8];
    int warp = tid >> 5, lane = tid & 31;
    if (lane == 0) wsum[warp] = ss;
    __syncthreads();
    float tot = 0.f;
    #pragma unroll
    for (int i = 0; i < 8; i++) tot += wsum[i];

    float inv = rsqrtf(tot * (1.0f / (float)D_MODEL) + EPS);

    float4 g = gp[tid];
    float4 o;
    o.x = v.x * inv * g.x;
    o.y = v.y * inv * g.y;
    o.z = v.z * inv * g.z;
    o.w = v.w * inv * g.w;
    yp[tid] = o;
}

// ---------------------------------------------------------------------------
// SGEMM: C[M,N] = A[M,K] @ B[K,N] with epilogue modes.
//   MODE 0: C = acc
//   MODE 1: C = acc + R          (residual add)
//   MODE 2: C = silu(acc)        (silu store)
//   MODE 3: C = C * acc          (multiply into existing C)
// 128x128 tile, BK=8, 256 threads, 8x8 microtile. M,K assumed %128/%8; N guarded.
// ---------------------------------------------------------------------------
#define BM 128
#define BN 128
#define GK 8
#define TM 8
#define TN 8

template<int MODE>
__global__ __launch_bounds__(256)
void sgemm_kernel(const float* __restrict__ A, const float* __restrict__ B,
                  float* __restrict__ C, const float* __restrict__ R,
                  int M, int N, int K)
{
    __shared__ float As[GK][BM];
    __shared__ float Bs[GK][BN];

    int tid = threadIdx.x;
    int bm  = blockIdx.y * BM;
    int bn  = blockIdx.x * BN;

    // A tile load: 128 rows x 8 cols = 1024 floats = 256 float4
    int arow = tid >> 1;
    int acol = (tid & 1) * 4;
    // B tile load: 8 rows x 128 cols = 1024 floats = 256 float4
    int brow = tid >> 5;
    int bcol = (tid & 31) * 4;

    int tx = tid & 15;        // 0..15 -> N
    int ty = tid >> 4;        // 0..15 -> M

    float acc[TM][TN];
    #pragma unroll
    for (int i = 0; i < TM; i++)
        #pragma unroll
        for (int j = 0; j < TN; j++) acc[i][j] = 0.f;

    const float* Arow = A + (size_t)(bm + arow) * K;

    for (int k0 = 0; k0 < K; k0 += GK) {
        // --- load A tile (transposed into smem) ---
        float4 av = *reinterpret_cast<const float4*>(Arow + k0 + acol);
        As[acol + 0][arow] = av.x;
        As[acol + 1][arow] = av.y;
        As[acol + 2][arow] = av.z;
        As[acol + 3][arow] = av.w;
        // --- load B tile ---
        int gn = bn + bcol;
        float4 bv;
        if (gn < N)
            bv = *reinterpret_cast<const float4*>(B + (size_t)(k0 + brow) * N + gn);
        else
            bv = make_float4(0.f, 0.f, 0.f, 0.f);
        *reinterpret_cast<float4*>(&Bs[brow][bcol]) = bv;

        __syncthreads();

        #pragma unroll
        for (int k = 0; k < GK; k++) {
            float4 a0 = *reinterpret_cast<const float4*>(&As[k][ty * TM]);
            float4 a1 = *reinterpret_cast<const float4*>(&As[k][ty * TM + 4]);
            float4 b0 = *reinterpret_cast<const float4*>(&Bs[k][tx * TN]);
            float4 b1 = *reinterpret_cast<const float4*>(&Bs[k][tx * TN + 4]);
            float ra[TM] = {a0.x, a0.y, a0.z, a0.w, a1.x, a1.y, a1.z, a1.w};
            float rb[TN] = {b0.x, b0.y, b0.z, b0.w, b1.x, b1.y, b1.z, b1.w};
            #pragma unroll
            for (int i = 0; i < TM; i++)
                #pragma unroll
                for (int j = 0; j < TN; j++)
                    acc[i][j] += ra[i] * rb[j];
        }
        __syncthreads();
    }

    // --- epilogue ---
    #pragma unroll
    for (int i = 0; i < TM; i++) {
        int m = bm + ty * TM + i;
        size_t rowoff = (size_t)m * N;
        #pragma unroll
        for (int j = 0; j < TN; j++) {
            int n = bn + tx * TN + j;
            if (n < N) {
                size_t idx = rowoff + n;
                float v = acc[i][j];
                if (MODE == 0) {
                    C[idx] = v;
                } else if (MODE == 1) {
                    C[idx] = v + R[idx];
                } else if (MODE == 2) {
                    C[idx] = v / (1.0f + __expf(-v));
                } else { // MODE 3
                    C[idx] = C[idx] * v;
                }
            }
        }
    }
}

// ---------------------------------------------------------------------------
// Causal flash attention, fp32. 1 thread = 1 query row.
// grid: (SEQ/128, BATCH*N_HEADS), block: 128 threads.
// Q,K,V stored as [B*S, D_MODEL] row-major; head h occupies cols [h*64, h*64+64).
// Output written to same layout (== (b,s,h,dh) flattened == (b,s,d)).
// ---------------------------------------------------------------------------
#define AQ 128
#define AK 64

__global__ __launch_bounds__(128)
void attn_kernel(const float* __restrict__ Q, const float* __restrict__ Kb,
                 const float* __restrict__ Vb, float* __restrict__ O)
{
    __shared__ float Ks[AK][D_HEAD];
    __shared__ float Vs[AK][D_HEAD];

    int bh  = blockIdx.y;
    int b   = bh >> 4;
    int h   = bh & 15;
    int q0  = blockIdx.x * AQ;
    int tid = threadIdx.x;

    int qrow = q0 + tid;                           // sequence position
    size_t mrow = (size_t)(b * SEQ + qrow);
    const float4* qp = reinterpret_cast<const float4*>(Q + mrow * D_MODEL + h * D_HEAD);

    float4 q4[16];
    #pragma unroll
    for (int i = 0; i < 16; i++) q4[i] = qp[i];

    float4 o4[16];
    #pragma unroll
    for (int i = 0; i < 16; i++) o4[i] = make_float4(0.f, 0.f, 0.f, 0.f);

    float mmax = -1e30f;
    float l = 0.f;

    int nkt = q0 / AK + 2;                         // tiles covering keys <= q0+127
    for (int kt = 0; kt < nkt; kt++) {
        int k0 = kt * AK;
        __syncthreads();
        // cooperative load of K and V tiles: AK rows x 16 float4 each
        for (int i = tid; i < AK * 16; i += 128) {
            int r = i >> 4;
            int c = i & 15;
            size_t grow = (size_t)(b * SEQ + k0 + r) * D_MODEL + h * D_HEAD;
            reinterpret_cast<float4*>(Ks[r])[c] =
                reinterpret_cast<const float4*>(Kb + grow)[c];
            reinterpret_cast<float4*>(Vs[r])[c] =
                reinterpret_cast<const float4*>(Vb + grow)[c];
        }
        __syncthreads();

        int jmax = qrow - k0 + 1;
        if (jmax > AK) jmax = AK;
        for (int j = 0; j < jmax; j++) {
            const float4* kr = reinterpret_cast<const float4*>(Ks[j]);
            float s = 0.f;
            #pragma unroll
            for (int i = 0; i < 16; i++) {
                float4 kv = kr[i];
                s += q4[i].x * kv.x + q4[i].y * kv.y
                   + q4[i].z * kv.z + q4[i].w * kv.w;
            }
            s *= 0.125f;                           // 1/sqrt(64)
            if (s > mmax) {
                float corr = __expf(mmax - s);
                l *= corr;
                #pragma unroll
                for (int i = 0; i < 16; i++) {
                    o4[i].x *= corr; o4[i].y *= corr;
                    o4[i].z *= corr; o4[i].w *= corr;
                }
                mmax = s;
            }
            float p = __expf(s - mmax);
            l += p;
            const float4* vr = reinterpret_cast<const float4*>(Vs[j]);
            #pragma unroll
            for (int i = 0; i < 16; i++) {
                float4 vv = vr[i];
                o4[i].x += p * vv.x; o4[i].y += p * vv.y;
                o4[i].z += p * vv.z; o4[i].w += p * vv.w;
            }
        }
    }

    float inv = 1.0f / l;
    float4* op = reinterpret_cast<float4*>(O + mrow * D_MODEL + h * D_HEAD);
    #pragma unroll
    for (int i = 0; i < 16; i++) {
        float4 o = o4[i];
        o.x *= inv; o.y *= inv; o.z *= inv; o.w *= inv;
        op[i] = o;
    }
}

// ---------------------------------------------------------------------------
// Launch
// ---------------------------------------------------------------------------
extern "C" void kernel_launch(void* const* d_in, const int* in_sizes, int n_in,
                              void* d_out, int out_size)
{
    const float* x  = (const float*)d_in[0];
    const float* g1 = (const float*)d_in[1];
    const float* g2 = (const float*)d_in[2];
    const float* wq = (const float*)d_in[3];
    const float* wk = (const float*)d_in[4];
    const float* wv = (const float*)d_in[5];
    const float* wo = (const float*)d_in[6];
    const float* w1 = (const float*)d_in[7];
    const float* w2 = (const float*)d_in[8];
    const float* w3 = (const float*)d_in[9];
    float* out = (float*)d_out;

    float *xn, *q, *k, *v, *attn, *hres, *hn, *gate;
    cudaGetSymbolAddress((void**)&xn,   g_xn);
    cudaGetSymbolAddress((void**)&q,    g_q);
    cudaGetSymbolAddress((void**)&k,    g_k);
    cudaGetSymbolAddress((void**)&v,    g_v);
    cudaGetSymbolAddress((void**)&attn, g_attn);
    cudaGetSymbolAddress((void**)&hres, g_hres);
    cudaGetSymbolAddress((void**)&hn,   g_hn);
    cudaGetSymbolAddress((void**)&gate, g_gate);

    dim3 gD((D_MODEL + BN - 1) / BN, ROWS / BM);     // (8, 32)
    dim3 gF((D_FF + BN - 1) / BN,  ROWS / BM);       // (22, 32)

    // 1. norm1
    rmsnorm_kernel<<<ROWS, 256>>>(x, g1, xn);

    // 2-4. Q/K/V projections
    sgemm_kernel<0><<<gD, 256>>>(xn, wq, q, nullptr, ROWS, D_MODEL, D_MODEL);
    sgemm_kernel<0><<<gD, 256>>>(xn, wk, k, nullptr, ROWS, D_MODEL, D_MODEL);
    sgemm_kernel<0><<<gD, 256>>>(xn, wv, v, nullptr, ROWS, D_MODEL, D_MODEL);

    // 5. causal attention
    dim3 gA(SEQ / AQ, BATCH * N_HEADS);              // (16, 32)
    attn_kernel<<<gA, 128>>>(q, k, v, attn);

    // 6. output projection + residual: hres = x + attn @ wo
    sgemm_kernel<1><<<gD, 256>>>(attn, wo, hres, x, ROWS, D_MODEL, D_MODEL);

    // 7. norm2
    rmsnorm_kernel<<<ROWS, 256>>>(hres, g2, hn);

    // 8. gate = silu(hn @ w1)
    sgemm_kernel<2><<<gF, 256>>>(hn, w1, gate, nullptr, ROWS, D_FF, D_MODEL);

    // 9. gate *= hn @ w3
    sgemm_kernel<3><<<gF, 256>>>(hn, w3, gate, nullptr, ROWS, D_FF, D_MODEL);

    // 10. out = hres + gate @ w2
    sgemm_kernel<1><<<gD, 256>>>(gate, w2, out, hres, ROWS, D_MODEL, D_FF);
}

// round 4
// speedup vs baseline: 2.0747x; 2.0747x over previous
#include <cuda_runtime.h>
#include <cuda_bf16.h>
#include <stdint.h>
#include <math.h>

// ---------------------------------------------------------------------------
// Problem constants
// ---------------------------------------------------------------------------
#define D_MODEL 1024
#define N_HEADS 16
#define D_HEAD  64
#define D_FF    2752
#define BATCH   2
#define SEQ     2048
#define ROWS    (BATCH * SEQ)          // 4096
#define EPS     1e-5f

// ---------------------------------------------------------------------------
// Scratch (device globals; no allocation allowed)
// ---------------------------------------------------------------------------
__device__ float g_xn  [ROWS * D_MODEL];
__device__ float g_q   [ROWS * D_MODEL];
__device__ float g_k   [ROWS * D_MODEL];
__device__ float g_v   [ROWS * D_MODEL];
__device__ float g_attn[ROWS * D_MODEL];
__device__ float g_hres[ROWS * D_MODEL];
__device__ float g_hn  [ROWS * D_MODEL];
__device__ float g_gate[ROWS * D_FF];

// ---------------------------------------------------------------------------
// RMSNorm: one block per row of 1024, 256 threads, float4
// ---------------------------------------------------------------------------
__global__ void rmsnorm_kernel(const float* __restrict__ X,
                               const float* __restrict__ G,
                               float* __restrict__ Y)
{
    int row = blockIdx.x;
    int tid = threadIdx.x;                       // 256
    const float4* xp = reinterpret_cast<const float4*>(X + (size_t)row * D_MODEL);
    const float4* gp = reinterpret_cast<const float4*>(G);
    float4*       yp = reinterpret_cast<float4*>(Y + (size_t)row * D_MODEL);

    float4 v = xp[tid];
    float ss = v.x * v.x + v.y * v.y + v.z * v.z + v.w * v.w;

    #pragma unroll
    for (int off = 16; off > 0; off >>= 1)
        ss += __shfl_xor_sync(0xffffffffu, ss, off);

    __shared__ float wsum[8];
    int warp = tid >> 5, lane = tid & 31;
    if (lane == 0) wsum[warp] = ss;
    __syncthreads();
    float tot = 0.f;
    #pragma unroll
    for (int i = 0; i < 8; i++) tot += wsum[i];

    float inv = rsqrtf(tot * (1.0f / (float)D_MODEL) + EPS);

    float4 g = gp[tid];
    float4 o;
    o.x = v.x * inv * g.x;
    o.y = v.y * inv * g.y;
    o.z = v.z * inv * g.z;
    o.w = v.w * inv * g.w;
    yp[tid] = o;
}

// ---------------------------------------------------------------------------
// TF32 tensor-core GEMM: C[M,N] = A[M,K] @ B[K,N], epilogue modes.
//   MODE 0: C = acc
//   MODE 1: C = acc + R          (residual add)
//   MODE 2: C = silu(acc)        (silu store)
//   MODE 3: C = C * acc          (multiply into existing C)
// Block tile 128x128, BK=32, 256 threads = 8 warps (2x4), warp tile 64x32,
// mma.sync.aligned.m16n8k8.row.col.f32.tf32.tf32.f32.
// Requirements: M%128==0, K%32==0 (true for all calls). N guarded (N%8==0).
// ---------------------------------------------------------------------------
#define BM 128
#define BN 128
#define BK 32
#define AST 36     // As row stride (floats): BK+4, 16B-aligned, low conflicts
#define BST 136    // Bs row stride (floats): BN+8, conflict-free frag loads

__device__ __forceinline__ float to_tf32(float x)
{
    float r;
    asm("cvt.rna.tf32.f32 %0, %1;" : "=f"(r) : "f"(x));
    return r;
}

__device__ __forceinline__ void mma_tf32(float c[4],
                                         unsigned int a0, unsigned int a1,
                                         unsigned int a2, unsigned int a3,
                                         unsigned int b0, unsigned int b1)
{
    asm volatile(
        "mma.sync.aligned.m16n8k8.row.col.f32.tf32.tf32.f32 "
        "{%0,%1,%2,%3}, {%4,%5,%6,%7}, {%8,%9}, {%0,%1,%2,%3};"
        : "+f"(c[0]), "+f"(c[1]), "+f"(c[2]), "+f"(c[3])
        : "r"(a0), "r"(a1), "r"(a2), "r"(a3), "r"(b0), "r"(b1));
}

template<int MODE>
__global__ __launch_bounds__(256)
void tgemm_kernel(const float* __restrict__ A, const float* __restrict__ B,
                  float* __restrict__ C, const float* __restrict__ R,
                  int M, int N, int K)
{
    __shared__ float As[BM * AST];   // [m][k] row-major, stride 36
    __shared__ float Bs[BK * BST];   // [k][n] row-major, stride 136

    int tid  = threadIdx.x;
    int lane = tid & 31;
    int warp = tid >> 5;             // 0..7
    int wm   = warp >> 2;            // 0..1  (M dir, 64 rows each)
    int wn   = warp & 3;             // 0..3  (N dir, 32 cols each)
    int grp  = lane >> 2;            // 0..7
    int qid  = lane & 3;             // 0..3

    int bm = blockIdx.y * BM;
    int bn = blockIdx.x * BN;

    float acc[4][4][4];              // [mi][ni][c0..c3]
    #pragma unroll
    for (int mi = 0; mi < 4; mi++)
        #pragma unroll
        for (int ni = 0; ni < 4; ni++)
            #pragma unroll
            for (int c = 0; c < 4; c++) acc[mi][ni][c] = 0.f;

    // --- global load staging ---
    // A tile: 128x32 floats = 1024 float4; thread handles 4 (idx = tid + 256*i)
    // B tile: 32x128 floats = 1024 float4
    float4 pa[4], pb[4];

    auto load_global = [&](int k0) {
        #pragma unroll
        for (int i = 0; i < 4; i++) {
            int idx = tid + (i << 8);
            int m = idx >> 3, kq = idx & 7;
            pa[i] = *reinterpret_cast<const float4*>(
                A + (size_t)(bm + m) * K + k0 + (kq << 2));
        }
        #pragma unroll
        for (int i = 0; i < 4; i++) {
            int idx = tid + (i << 8);
            int r = idx >> 5, nq = idx & 31;
            int gn = bn + (nq << 2);
            if (gn < N)
                pb[i] = *reinterpret_cast<const float4*>(
                    B + (size_t)(k0 + r) * N + gn);
            else
                pb[i] = make_float4(0.f, 0.f, 0.f, 0.f);
        }
    };

    auto store_smem = [&]() {
        #pragma unroll
        for (int i = 0; i < 4; i++) {
            int idx = tid + (i << 8);
            int m = idx >> 3, kq = idx & 7;
            float4 v = pa[i];
            v.x = to_tf32(v.x); v.y = to_tf32(v.y);
            v.z = to_tf32(v.z); v.w = to_tf32(v.w);
            *reinterpret_cast<float4*>(&As[m * AST + (kq << 2)]) = v;
        }
        #pragma unroll
        for (int i = 0; i < 4; i++) {
            int idx = tid + (i << 8);
            int r = idx >> 5, nq = idx & 31;
            float4 v = pb[i];
            v.x = to_tf32(v.x); v.y = to_tf32(v.y);
            v.z = to_tf32(v.z); v.w = to_tf32(v.w);
            *reinterpret_cast<float4*>(&Bs[r * BST + (nq << 2)]) = v;
        }
    };

    load_global(0);
    store_smem();
    __syncthreads();

    int arow = wm * 64 + grp;        // base row within tile for a-frags
    int ncol = wn * 32 + grp;        // base col within tile for b-frags

    for (int k0 = 0; k0 < K; k0 += BK) {
        bool more = (k0 + BK) < K;
        if (more) load_global(k0 + BK);

        #pragma unroll
        for (int kk = 0; kk < 4; kk++) {
            int kb = kk << 3;
            unsigned int af[4][4];
            #pragma unroll
            for (int mi = 0; mi < 4; mi++) {
                const float* ap = &As[(arow + mi * 16) * AST + kb + qid];
                af[mi][0] = __float_as_uint(ap[0]);
                af[mi][1] = __float_as_uint(ap[8 * AST]);
                af[mi][2] = __float_as_uint(ap[4]);
                af[mi][3] = __float_as_uint(ap[8 * AST + 4]);
            }
            #pragma unroll
            for (int ni = 0; ni < 4; ni++) {
                const float* bp = &Bs[(kb + qid) * BST + ncol + ni * 8];
                unsigned int b0 = __float_as_uint(bp[0]);
                unsigned int b1 = __float_as_uint(bp[4 * BST]);
                #pragma unroll
                for (int mi = 0; mi < 4; mi++)
                    mma_tf32(acc[mi][ni], af[mi][0], af[mi][1], af[mi][2], af[mi][3], b0, b1);
            }
        }

        __syncthreads();
        if (more) {
            store_smem();
            __syncthreads();
        }
    }

    // --- epilogue: each (mi,ni) frag covers rows {r, r+8}, cols {c, c+1} ---
    #pragma unroll
    for (int mi = 0; mi < 4; mi++) {
        #pragma unroll
        for (int ni = 0; ni < 4; ni++) {
            int n = bn + wn * 32 + ni * 8 + qid * 2;
            if (n < N) {   // N%8==0, so whole 8-col frag is in or out
                #pragma unroll
                for (int half = 0; half < 2; half++) {
                    int m = bm + wm * 64 + mi * 16 + grp + half * 8;
                    size_t idx = (size_t)m * N + n;
                    float v0 = acc[mi][ni][half * 2 + 0];
                    float v1 = acc[mi][ni][half * 2 + 1];
                    float2 o;
                    if (MODE == 0) {
                        o.x = v0; o.y = v1;
                    } else if (MODE == 1) {
                        const float2 r2 = *reinterpret_cast<const float2*>(&R[idx]);
                        o.x = v0 + r2.x; o.y = v1 + r2.y;
                    } else if (MODE == 2) {
                        o.x = v0 / (1.0f + __expf(-v0));
                        o.y = v1 / (1.0f + __expf(-v1));
                    } else { // MODE 3
                        const float2 c2 = *reinterpret_cast<const float2*>(&C[idx]);
                        o.x = c2.x * v0; o.y = c2.y * v1;
                    }
                    *reinterpret_cast<float2*>(&C[idx]) = o;
                }
            }
        }
    }
}

// ---------------------------------------------------------------------------
// Causal flash attention, fp32. 1 thread = 1 query row.
// ---------------------------------------------------------------------------
#define AQ 128
#define AK 64

__global__ __launch_bounds__(128)
void attn_kernel(const float* __restrict__ Q, const float* __restrict__ Kb,
                 const float* __restrict__ Vb, float* __restrict__ O)
{
    __shared__ float Ks[AK][D_HEAD];
    __shared__ float Vs[AK][D_HEAD];

    int bh  = blockIdx.y;
    int b   = bh >> 4;
    int h   = bh & 15;
    int q0  = blockIdx.x * AQ;
    int tid = threadIdx.x;

    int qrow = q0 + tid;
    size_t mrow = (size_t)(b * SEQ + qrow);
    const float4* qp = reinterpret_cast<const float4*>(Q + mrow * D_MODEL + h * D_HEAD);

    float4 q4[16];
    #pragma unroll
    for (int i = 0; i < 16; i++) q4[i] = qp[i];

    float4 o4[16];
    #pragma unroll
    for (int i = 0; i < 16; i++) o4[i] = make_float4(0.f, 0.f, 0.f, 0.f);

    float mmax = -1e30f;
    float l = 0.f;

    int nkt = q0 / AK + 2;
    for (int kt = 0; kt < nkt; kt++) {
        int k0 = kt * AK;
        __syncthreads();
        for (int i = tid; i < AK * 16; i += 128) {
            int r = i >> 4;
            int c = i & 15;
            size_t grow = (size_t)(b * SEQ + k0 + r) * D_MODEL + h * D_HEAD;
            reinterpret_cast<float4*>(Ks[r])[c] =
                reinterpret_cast<const float4*>(Kb + grow)[c];
            reinterpret_cast<float4*>(Vs[r])[c] =
                reinterpret_cast<const float4*>(Vb + grow)[c];
        }
        __syncthreads();

        int jmax = qrow - k0 + 1;
        if (jmax > AK) jmax = AK;
        for (int j = 0; j < jmax; j++) {
            const float4* kr = reinterpret_cast<const float4*>(Ks[j]);
            float s = 0.f;
            #pragma unroll
            for (int i = 0; i < 16; i++) {
                float4 kv = kr[i];
                s += q4[i].x * kv.x + q4[i].y * kv.y
                   + q4[i].z * kv.z + q4[i].w * kv.w;
            }
            s *= 0.125f;
            if (s > mmax) {
                float corr = __expf(mmax - s);
                l *= corr;
                #pragma unroll
                for (int i = 0; i < 16; i++) {
                    o4[i].x *= corr; o4[i].y *= corr;
                    o4[i].z *= corr; o4[i].w *= corr;
                }
                mmax = s;
            }
            float p = __expf(s - mmax);
            l += p;
            const float4* vr = reinterpret_cast<const float4*>(Vs[j]);
            #pragma unroll
            for (int i = 0; i < 16; i++) {
                float4 vv = vr[i];
                o4[i].x += p * vv.x; o4[i].y += p * vv.y;
                o4[i].z += p * vv.z; o4[i].w += p * vv.w;
            }
        }
    }

    float inv = 1.0f / l;
    float4* op = reinterpret_cast<float4*>(O + mrow * D_MODEL + h * D_HEAD);
    #pragma unroll
    for (int i = 0; i < 16; i++) {
        float4 o = o4[i];
        o.x *= inv; o.y *= inv; o.z *= inv; o.w *= inv;
        op[i] = o;
    }
}

// ---------------------------------------------------------------------------
// Launch
// ---------------------------------------------------------------------------
extern "C" void kernel_launch(void* const* d_in, const int* in_sizes, int n_in,
                              void* d_out, int out_size)
{
    const float* x  = (const float*)d_in[0];
    const float* g1 = (const float*)d_in[1];
    const float* g2 = (const float*)d_in[2];
    const float* wq = (const float*)d_in[3];
    const float* wk = (const float*)d_in[4];
    const float* wv = (const float*)d_in[5];
    const float* wo = (const float*)d_in[6];
    const float* w1 = (const float*)d_in[7];
    const float* w2 = (const float*)d_in[8];
    const float* w3 = (const float*)d_in[9];
    float* out = (float*)d_out;

    float *xn, *q, *k, *v, *attn, *hres, *hn, *gate;
    cudaGetSymbolAddress((void**)&xn,   g_xn);
    cudaGetSymbolAddress((void**)&q,    g_q);
    cudaGetSymbolAddress((void**)&k,    g_k);
    cudaGetSymbolAddress((void**)&v,    g_v);
    cudaGetSymbolAddress((void**)&attn, g_attn);
    cudaGetSymbolAddress((void**)&hres, g_hres);
    cudaGetSymbolAddress((void**)&hn,   g_hn);
    cudaGetSymbolAddress((void**)&gate, g_gate);

    dim3 gD((D_MODEL + BN - 1) / BN, ROWS / BM);     // (8, 32)
    dim3 gF((D_FF + BN - 1) / BN,  ROWS / BM);       // (22, 32)

    // 1. norm1
    rmsnorm_kernel<<<ROWS, 256>>>(x, g1, xn);

    // 2-4. Q/K/V projections
    tgemm_kernel<0><<<gD, 256>>>(xn, wq, q, nullptr, ROWS, D_MODEL, D_MODEL);
    tgemm_kernel<0><<<gD, 256>>>(xn, wk, k, nullptr, ROWS, D_MODEL, D_MODEL);
    tgemm_kernel<0><<<gD, 256>>>(xn, wv, v, nullptr, ROWS, D_MODEL, D_MODEL);

    // 5. causal attention
    dim3 gA(SEQ / AQ, BATCH * N_HEADS);              // (16, 32)
    attn_kernel<<<gA, 128>>>(q, k, v, attn);

    // 6. output projection + residual: hres = x + attn @ wo
    tgemm_kernel<1><<<gD, 256>>>(attn, wo, hres, x, ROWS, D_MODEL, D_MODEL);

    // 7. norm2
    rmsnorm_kernel<<<ROWS, 256>>>(hres, g2, hn);

    // 8. gate = silu(hn @ w1)
    tgemm_kernel<2><<<gF, 256>>>(hn, w1, gate, nullptr, ROWS, D_FF, D_MODEL);

    // 9. gate *= hn @ w3
    tgemm_kernel<3><<<gF, 256>>>(hn, w3, gate, nullptr, ROWS, D_FF, D_MODEL);

    // 10. out = hres + gate @ w2
    tgemm_kernel<1><<<gD, 256>>>(gate, w2, out, hres, ROWS, D_MODEL, D_FF);
}

// round 7
// speedup vs baseline: 3.7966x; 1.8299x over previous
#include <cuda_runtime.h>
#include <cuda_bf16.h>
#include <cuda_fp16.h>
#include <stdint.h>
#include <math.h>

// ---------------------------------------------------------------------------
// Problem constants
// ---------------------------------------------------------------------------
#define D_MODEL 1024
#define N_HEADS 16
#define D_HEAD  64
#define D_FF    2752
#define BATCH   2
#define SEQ     2048
#define ROWS    (BATCH * SEQ)          // 4096
#define EPS     1e-5f

// ---------------------------------------------------------------------------
// Scratch (device globals; no allocation allowed)
// ---------------------------------------------------------------------------
__device__ float g_xn  [ROWS * D_MODEL];
__device__ float g_q   [ROWS * D_MODEL];
__device__ float g_k   [ROWS * D_MODEL];
__device__ float g_v   [ROWS * D_MODEL];
__device__ float g_attn[ROWS * D_MODEL];
__device__ float g_hres[ROWS * D_MODEL];
__device__ float g_hn  [ROWS * D_MODEL];
__device__ float g_gate[ROWS * D_FF];

// ---------------------------------------------------------------------------
// RMSNorm
// ---------------------------------------------------------------------------
__global__ void rmsnorm_kernel(const float* __restrict__ X,
                               const float* __restrict__ G,
                               float* __restrict__ Y)
{
    int row = blockIdx.x;
    int tid = threadIdx.x;
    const float4* xp = reinterpret_cast<const float4*>(X + (size_t)row * D_MODEL);
    const float4* gp = reinterpret_cast<const float4*>(G);
    float4*       yp = reinterpret_cast<float4*>(Y + (size_t)row * D_MODEL);

    float4 v = xp[tid];
    float ss = v.x * v.x + v.y * v.y + v.z * v.z + v.w * v.w;

    #pragma unroll
    for (int off = 16; off > 0; off >>= 1)
        ss += __shfl_xor_sync(0xffffffffu, ss, off);

    __shared__ float wsum[8];
    int warp = tid >> 5, lane = tid & 31;
    if (lane == 0) wsum[warp] = ss;
    __syncthreads();
    float tot = 0.f;
    #pragma unroll
    for (int i = 0; i < 8; i++) tot += wsum[i];

    float inv = rsqrtf(tot * (1.0f / (float)D_MODEL) + EPS);

    float4 g = gp[tid];
    float4 o;
    o.x = v.x * inv * g.x;
    o.y = v.y * inv * g.y;
    o.z = v.z * inv * g.z;
    o.w = v.w * inv * g.w;
    yp[tid] = o;
}

// ---------------------------------------------------------------------------
// TF32 tensor-core GEMM (unchanged from R4)
// ---------------------------------------------------------------------------
#define BM 128
#define BN 128
#define BK 32
#define AST 36
#define BST 136

__device__ __forceinline__ float to_tf32(float x)
{
    float r;
    asm("cvt.rna.tf32.f32 %0, %1;" : "=f"(r) : "f"(x));
    return r;
}

__device__ __forceinline__ void mma_tf32(float c[4],
                                         unsigned int a0, unsigned int a1,
                                         unsigned int a2, unsigned int a3,
                                         unsigned int b0, unsigned int b1)
{
    asm volatile(
        "mma.sync.aligned.m16n8k8.row.col.f32.tf32.tf32.f32 "
        "{%0,%1,%2,%3}, {%4,%5,%6,%7}, {%8,%9}, {%0,%1,%2,%3};"
        : "+f"(c[0]), "+f"(c[1]), "+f"(c[2]), "+f"(c[3])
        : "r"(a0), "r"(a1), "r"(a2), "r"(a3), "r"(b0), "r"(b1));
}

template<int MODE>
__global__ __launch_bounds__(256)
void tgemm_kernel(const float* __restrict__ A, const float* __restrict__ B,
                  float* __restrict__ C, const float* __restrict__ R,
                  int M, int N, int K)
{
    __shared__ float As[BM * AST];
    __shared__ float Bs[BK * BST];

    int tid  = threadIdx.x;
    int lane = tid & 31;
    int warp = tid >> 5;
    int wm   = warp >> 2;
    int wn   = warp & 3;
    int grp  = lane >> 2;
    int qid  = lane & 3;

    int bm = blockIdx.y * BM;
    int bn = blockIdx.x * BN;

    float acc[4][4][4];
    #pragma unroll
    for (int mi = 0; mi < 4; mi++)
        #pragma unroll
        for (int ni = 0; ni < 4; ni++)
            #pragma unroll
            for (int c = 0; c < 4; c++) acc[mi][ni][c] = 0.f;

    float4 pa[4], pb[4];

    auto load_global = [&](int k0) {
        #pragma unroll
        for (int i = 0; i < 4; i++) {
            int idx = tid + (i << 8);
            int m = idx >> 3, kq = idx & 7;
            pa[i] = *reinterpret_cast<const float4*>(
                A + (size_t)(bm + m) * K + k0 + (kq << 2));
        }
        #pragma unroll
        for (int i = 0; i < 4; i++) {
            int idx = tid + (i << 8);
            int r = idx >> 5, nq = idx & 31;
            int gn = bn + (nq << 2);
            if (gn < N)
                pb[i] = *reinterpret_cast<const float4*>(
                    B + (size_t)(k0 + r) * N + gn);
            else
                pb[i] = make_float4(0.f, 0.f, 0.f, 0.f);
        }
    };

    auto store_smem = [&]() {
        #pragma unroll
        for (int i = 0; i < 4; i++) {
            int idx = tid + (i << 8);
            int m = idx >> 3, kq = idx & 7;
            float4 v = pa[i];
            v.x = to_tf32(v.x); v.y = to_tf32(v.y);
            v.z = to_tf32(v.z); v.w = to_tf32(v.w);
            *reinterpret_cast<float4*>(&As[m * AST + (kq << 2)]) = v;
        }
        #pragma unroll
        for (int i = 0; i < 4; i++) {
            int idx = tid + (i << 8);
            int r = idx >> 5, nq = idx & 31;
            float4 v = pb[i];
            v.x = to_tf32(v.x); v.y = to_tf32(v.y);
            v.z = to_tf32(v.z); v.w = to_tf32(v.w);
            *reinterpret_cast<float4*>(&Bs[r * BST + (nq << 2)]) = v;
        }
    };

    load_global(0);
    store_smem();
    __syncthreads();

    int arow = wm * 64 + grp;
    int ncol = wn * 32 + grp;

    for (int k0 = 0; k0 < K; k0 += BK) {
        bool more = (k0 + BK) < K;
        if (more) load_global(k0 + BK);

        #pragma unroll
        for (int kk = 0; kk < 4; kk++) {
            int kb = kk << 3;
            unsigned int af[4][4];
            #pragma unroll
            for (int mi = 0; mi < 4; mi++) {
                const float* ap = &As[(arow + mi * 16) * AST + kb + qid];
                af[mi][0] = __float_as_uint(ap[0]);
                af[mi][1] = __float_as_uint(ap[8 * AST]);
                af[mi][2] = __float_as_uint(ap[4]);
                af[mi][3] = __float_as_uint(ap[8 * AST + 4]);
            }
            #pragma unroll
            for (int ni = 0; ni < 4; ni++) {
                const float* bp = &Bs[(kb + qid) * BST + ncol + ni * 8];
                unsigned int b0 = __float_as_uint(bp[0]);
                unsigned int b1 = __float_as_uint(bp[4 * BST]);
                #pragma unroll
                for (int mi = 0; mi < 4; mi++)
                    mma_tf32(acc[mi][ni], af[mi][0], af[mi][1], af[mi][2], af[mi][3], b0, b1);
            }
        }

        __syncthreads();
        if (more) {
            store_smem();
            __syncthreads();
        }
    }

    #pragma unroll
    for (int mi = 0; mi < 4; mi++) {
        #pragma unroll
        for (int ni = 0; ni < 4; ni++) {
            int n = bn + wn * 32 + ni * 8 + qid * 2;
            if (n < N) {
                #pragma unroll
                for (int half = 0; half < 2; half++) {
                    int m = bm + wm * 64 + mi * 16 + grp + half * 8;
                    size_t idx = (size_t)m * N + n;
                    float v0 = acc[mi][ni][half * 2 + 0];
                    float v1 = acc[mi][ni][half * 2 + 1];
                    float2 o;
                    if (MODE == 0) {
                        o.x = v0; o.y = v1;
                    } else if (MODE == 1) {
                        const float2 r2 = *reinterpret_cast<const float2*>(&R[idx]);
                        o.x = v0 + r2.x; o.y = v1 + r2.y;
                    } else if (MODE == 2) {
                        o.x = v0 / (1.0f + __expf(-v0));
                        o.y = v1 / (1.0f + __expf(-v1));
                    } else {
                        const float2 c2 = *reinterpret_cast<const float2*>(&C[idx]);
                        o.x = c2.x * v0; o.y = c2.y * v1;
                    }
                    *reinterpret_cast<float2*>(&C[idx]) = o;
                }
            }
        }
    }
}

// ---------------------------------------------------------------------------
// Tensor-core causal flash attention (fp16 mma.m16n8k16, fp32 accumulate).
// BQ=64 query rows / block, 4 warps (16 rows each), BK=64 key tiles.
// grid: (SEQ/64, BATCH*N_HEADS), 128 threads.
// ---------------------------------------------------------------------------
#define AQ2 64
#define AK2 64
#define KST 72    // smem row stride in halves (144B: 16B aligned, ldmatrix conflict-free)

__device__ __forceinline__ unsigned smem_addr_u32(const void* p)
{
    return (unsigned)__cvta_generic_to_shared(p);
}

__device__ __forceinline__ void ldmx4(unsigned& r0, unsigned& r1,
                                      unsigned& r2, unsigned& r3, const __half* p)
{
    unsigned a = smem_addr_u32(p);
    asm volatile("ldmatrix.sync.aligned.m8n8.x4.shared.b16 {%0,%1,%2,%3}, [%4];"
                 : "=r"(r0), "=r"(r1), "=r"(r2), "=r"(r3) : "r"(a));
}

__device__ __forceinline__ void ldmx4t(unsigned& r0, unsigned& r1,
                                       unsigned& r2, unsigned& r3, const __half* p)
{
    unsigned a = smem_addr_u32(p);
    asm volatile("ldmatrix.sync.aligned.m8n8.x4.trans.shared.b16 {%0,%1,%2,%3}, [%4];"
                 : "=r"(r0), "=r"(r1), "=r"(r2), "=r"(r3) : "r"(a));
}

__device__ __forceinline__ void mma_f16(float c[4],
                                        unsigned a0, unsigned a1,
                                        unsigned a2, unsigned a3,
                                        unsigned b0, unsigned b1)
{
    asm volatile(
        "mma.sync.aligned.m16n8k16.row.col.f32.f16.f16.f32 "
        "{%0,%1,%2,%3}, {%4,%5,%6,%7}, {%8,%9}, {%0,%1,%2,%3};"
        : "+f"(c[0]), "+f"(c[1]), "+f"(c[2]), "+f"(c[3])
        : "r"(a0), "r"(a1), "r"(a2), "r"(a3), "r"(b0), "r"(b1));
}

__global__ __launch_bounds__(128)
void attn_mma_kernel(const float* __restrict__ Qg, const float* __restrict__ Kg,
                     const float* __restrict__ Vg, float* __restrict__ O)
{
    __shared__ __half Qs[AQ2 * KST];
    __shared__ __half Ks[AK2 * KST];
    __shared__ __half Vs[AK2 * KST];

    int bh  = blockIdx.y;
    int b   = bh >> 4;
    int h   = bh & 15;
    int bx  = blockIdx.x;
    int q0  = bx * AQ2;
    int tid = threadIdx.x;
    int lane = tid & 31;
    int w    = tid >> 5;          // warp 0..3, owns rows w*16..w*16+15
    int grp  = lane >> 2;         // 0..7
    int tig  = lane & 3;          // 0..3

    // --- stage Q tile: 64 rows x 64 cols fp32 -> fp16 smem ---
    for (int i = tid; i < AQ2 * 16; i += 128) {
        int r = i >> 4, c = i & 15;
        float4 f = *reinterpret_cast<const float4*>(
            Qg + (size_t)(b * SEQ + q0 + r) * D_MODEL + h * D_HEAD + 4 * c);
        __half2* dst = reinterpret_cast<__half2*>(&Qs[r * KST + 4 * c]);
        dst[0] = __floats2half2_rn(f.x, f.y);
        dst[1] = __floats2half2_rn(f.z, f.w);
    }
    __syncthreads();

    // --- Q fragments: 4 k-chunks of 16, ldmatrix x4 (non-trans) ---
    // addr: row = w*16 + (sel&1)*8 + r, col = 16*kc + (sel>>1)*8
    unsigned qf[4][4];
    {
        int r = lane & 7, sel = lane >> 3;
        int qrow = w * 16 + (sel & 1) * 8 + r;
        #pragma unroll
        for (int kc = 0; kc < 4; kc++) {
            int col = 16 * kc + (sel >> 1) * 8;
            ldmx4(qf[kc][0], qf[kc][1], qf[kc][2], qf[kc][3], &Qs[qrow * KST + col]);
        }
    }

    float oacc[8][4];
    #pragma unroll
    for (int d = 0; d < 8; d++)
        #pragma unroll
        for (int c = 0; c < 4; c++) oacc[d][c] = 0.f;

    float m0 = -1e30f, m1 = -1e30f;
    float l0 = 0.f,    l1 = 0.f;

    int qr0 = q0 + w * 16 + grp;   // row for c0/c1
    int qr1 = qr0 + 8;             // row for c2/c3

    for (int kt = 0; kt <= bx; kt++) {
        int k0 = kt * AK2;
        __syncthreads();
        // --- stage K, V tiles (fp32 -> fp16, coalesced) ---
        for (int i = tid; i < AK2 * 16; i += 128) {
            int r = i >> 4, c = i & 15;
            size_t goff = (size_t)(b * SEQ + k0 + r) * D_MODEL + h * D_HEAD + 4 * c;
            float4 fk = *reinterpret_cast<const float4*>(Kg + goff);
            float4 fv = *reinterpret_cast<const float4*>(Vg + goff);
            __half2* dk = reinterpret_cast<__half2*>(&Ks[r * KST + 4 * c]);
            dk[0] = __floats2half2_rn(fk.x, fk.y);
            dk[1] = __floats2half2_rn(fk.z, fk.w);
            __half2* dv = reinterpret_cast<__half2*>(&Vs[r * KST + 4 * c]);
            dv[0] = __floats2half2_rn(fv.x, fv.y);
            dv[1] = __floats2half2_rn(fv.z, fv.w);
        }
        __syncthreads();

        // --- S = Q K^T : 8 n-tiles (8 keys each) x 4 k-chunks ---
        float sacc[8][4];
        #pragma unroll
        for (int j = 0; j < 8; j++)
            #pragma unroll
            for (int c = 0; c < 4; c++) sacc[j][c] = 0.f;

        {
            int r = lane & 7, sel = lane >> 3;
            #pragma unroll
            for (int kc = 0; kc < 4; kc++) {
                #pragma unroll
                for (int jj = 0; jj < 4; jj++) {
                    // rows (keys) = 16*jj + (sel>>1)*8 + r, cols (dh) = 16*kc + (sel&1)*8
                    int krow = 16 * jj + (sel >> 1) * 8 + r;
                    int kcol = 16 * kc + (sel & 1) * 8;
                    unsigned b0a, b1a, b0b, b1b;
                    ldmx4(b0a, b1a, b0b, b1b, &Ks[krow * KST + kcol]);
                    mma_f16(sacc[2 * jj],     qf[kc][0], qf[kc][1], qf[kc][2], qf[kc][3], b0a, b1a);
                    mma_f16(sacc[2 * jj + 1], qf[kc][0], qf[kc][1], qf[kc][2], qf[kc][3], b0b, b1b);
                }
            }
        }

        // --- scale + causal mask (diagonal tile only) ---
        bool diag = (kt == bx);
        #pragma unroll
        for (int j = 0; j < 8; j++) {
            #pragma unroll
            for (int c = 0; c < 4; c++) sacc[j][c] *= 0.125f;
            if (diag) {
                int kc0 = k0 + 8 * j + 2 * tig;
                if (kc0     > qr0) sacc[j][0] = -1e30f;
                if (kc0 + 1 > qr0) sacc[j][1] = -1e30f;
                if (kc0     > qr1) sacc[j][2] = -1e30f;
                if (kc0 + 1 > qr1) sacc[j][3] = -1e30f;
            }
        }

        // --- online softmax ---
        float mx0 = -1e30f, mx1 = -1e30f;
        #pragma unroll
        for (int j = 0; j < 8; j++) {
            mx0 = fmaxf(mx0, fmaxf(sacc[j][0], sacc[j][1]));
            mx1 = fmaxf(mx1, fmaxf(sacc[j][2], sacc[j][3]));
        }
        mx0 = fmaxf(mx0, __shfl_xor_sync(0xffffffffu, mx0, 1));
        mx0 = fmaxf(mx0, __shfl_xor_sync(0xffffffffu, mx0, 2));
        mx1 = fmaxf(mx1, __shfl_xor_sync(0xffffffffu, mx1, 1));
        mx1 = fmaxf(mx1, __shfl_xor_sync(0xffffffffu, mx1, 2));

        float mn0 = fmaxf(m0, mx0);
        float mn1 = fmaxf(m1, mx1);
        float corr0 = __expf(m0 - mn0);
        float corr1 = __expf(m1 - mn1);
        m0 = mn0; m1 = mn1;

        unsigned ph[8][2];
        float rs0 = 0.f, rs1 = 0.f;
        #pragma unroll
        for (int j = 0; j < 8; j++) {
            float p0 = __expf(sacc[j][0] - m0);
            float p1 = __expf(sacc[j][1] - m0);
            float p2 = __expf(sacc[j][2] - m1);
            float p3 = __expf(sacc[j][3] - m1);
            rs0 += p0 + p1;
            rs1 += p2 + p3;
            __half2 h01 = __floats2half2_rn(p0, p1);
            __half2 h23 = __floats2half2_rn(p2, p3);
            ph[j][0] = *reinterpret_cast<unsigned*>(&h01);
            ph[j][1] = *reinterpret_cast<unsigned*>(&h23);
        }
        rs0 += __shfl_xor_sync(0xffffffffu, rs0, 1);
        rs0 += __shfl_xor_sync(0xffffffffu, rs0, 2);
        rs1 += __shfl_xor_sync(0xffffffffu, rs1, 1);
        rs1 += __shfl_xor_sync(0xffffffffu, rs1, 2);
        l0 = l0 * corr0 + rs0;
        l1 = l1 * corr1 + rs1;

        #pragma unroll
        for (int d = 0; d < 8; d++) {
            oacc[d][0] *= corr0; oacc[d][1] *= corr0;
            oacc[d][2] *= corr1; oacc[d][3] *= corr1;
        }

        // --- O += P V : A-frags = repacked S accumulators; B via ldmatrix.trans ---
        {
            int r = lane & 7, sel = lane >> 3;
            #pragma unroll
            for (int kc = 0; kc < 4; kc++) {
                unsigned a0 = ph[2 * kc][0];
                unsigned a1 = ph[2 * kc][1];
                unsigned a2 = ph[2 * kc + 1][0];
                unsigned a3 = ph[2 * kc + 1][1];
                #pragma unroll
                for (int dd = 0; dd < 4; dd++) {
                    // rows (keys) = 16*kc + (sel&1)*8 + r, cols (dh) = 16*dd + (sel>>1)*8
                    int vrow = 16 * kc + (sel & 1) * 8 + r;
                    int vcol = 16 * dd + (sel >> 1) * 8;
                    unsigned v0, v1, v2, v3;
                    ldmx4t(v0, v1, v2, v3, &Vs[vrow * KST + vcol]);
                    mma_f16(oacc[2 * dd],     a0, a1, a2, a3, v0, v1);
                    mma_f16(oacc[2 * dd + 1], a0, a1, a2, a3, v2, v3);
                }
            }
        }
    }

    // --- normalize + write ---
    float inv0 = 1.0f / l0;
    float inv1 = 1.0f / l1;
    size_t row0 = (size_t)(b * SEQ + qr0);
    size_t row1 = (size_t)(b * SEQ + qr1);
    #pragma unroll
    for (int d = 0; d < 8; d++) {
        int col = h * D_HEAD + 8 * d + 2 * tig;
        float2 o0 = make_float2(oacc[d][0] * inv0, oacc[d][1] * inv0);
        float2 o1 = make_float2(oacc[d][2] * inv1, oacc[d][3] * inv1);
        *reinterpret_cast<float2*>(O + row0 * D_MODEL + col) = o0;
        *reinterpret_cast<float2*>(O + row1 * D_MODEL + col) = o1;
    }
}

// ---------------------------------------------------------------------------
// Launch
// ---------------------------------------------------------------------------
extern "C" void kernel_launch(void* const* d_in, const int* in_sizes, int n_in,
                              void* d_out, int out_size)
{
    const float* x  = (const float*)d_in[0];
    const float* g1 = (const float*)d_in[1];
    const float* g2 = (const float*)d_in[2];
    const float* wq = (const float*)d_in[3];
    const float* wk = (const float*)d_in[4];
    const float* wv = (const float*)d_in[5];
    const float* wo = (const float*)d_in[6];
    const float* w1 = (const float*)d_in[7];
    const float* w2 = (const float*)d_in[8];
    const float* w3 = (const float*)d_in[9];
    float* out = (float*)d_out;

    float *xn, *q, *k, *v, *attn, *hres, *hn, *gate;
    cudaGetSymbolAddress((void**)&xn,   g_xn);
    cudaGetSymbolAddress((void**)&q,    g_q);
    cudaGetSymbolAddress((void**)&k,    g_k);
    cudaGetSymbolAddress((void**)&v,    g_v);
    cudaGetSymbolAddress((void**)&attn, g_attn);
    cudaGetSymbolAddress((void**)&hres, g_hres);
    cudaGetSymbolAddress((void**)&hn,   g_hn);
    cudaGetSymbolAddress((void**)&gate, g_gate);

    dim3 gD((D_MODEL + BN - 1) / BN, ROWS / BM);     // (8, 32)
    dim3 gF((D_FF + BN - 1) / BN,  ROWS / BM);       // (22, 32)

    // 1. norm1
    rmsnorm_kernel<<<ROWS, 256>>>(x, g1, xn);

    // 2-4. Q/K/V projections
    tgemm_kernel<0><<<gD, 256>>>(xn, wq, q, nullptr, ROWS, D_MODEL, D_MODEL);
    tgemm_kernel<0><<<gD, 256>>>(xn, wk, k, nullptr, ROWS, D_MODEL, D_MODEL);
    tgemm_kernel<0><<<gD, 256>>>(xn, wv, v, nullptr, ROWS, D_MODEL, D_MODEL);

    // 5. causal attention (tensor-core flash)
    dim3 gA(SEQ / AQ2, BATCH * N_HEADS);             // (32, 32)
    attn_mma_kernel<<<gA, 128>>>(q, k, v, attn);

    // 6. output projection + residual: hres = x + attn @ wo
    tgemm_kernel<1><<<gD, 256>>>(attn, wo, hres, x, ROWS, D_MODEL, D_MODEL);

    // 7. norm2
    rmsnorm_kernel<<<ROWS, 256>>>(hres, g2, hn);

    // 8. gate = silu(hn @ w1)
    tgemm_kernel<2><<<gF, 256>>>(hn, w1, gate, nullptr, ROWS, D_FF, D_MODEL);

    // 9. gate *= hn @ w3
    tgemm_kernel<3><<<gF, 256>>>(hn, w3, gate, nullptr, ROWS, D_FF, D_MODEL);

    // 10. out = hres + gate @ w2
    tgemm_kernel<1><<<gD, 256>>>(gate, w2, out, hres, ROWS, D_MODEL, D_FF);
}